// round 16
// baseline (speedup 1.0000x reference)
#include <cuda_runtime.h>
#include <cuda_fp16.h>
#include <math.h>

// HashGrid: 10-level Instant-NGP hash encoding, 2M points, FEAT_DIM=3.
// FINAL (converged; best measured 100.864us, reproduced twice): codebooks
// fp16-packed (8 B/entry) in shared memory, fp32 accumulation, compile-time
// level sizes (magic-number mod), static grid-stride, 2x512 threads/SM.
//
// Floor analysis (validated to ~2%): LDS crossbar bound at ~4.86 cyc per
// random 8B warp-gather (E[max load] over 16 bank pairs, 32 lanes), l1tex
// ~90% sustained + ~6% pipe share for coalesced point I/O. Falsified levers:
// spatial sort (R3-8: binning >= its benefit), instruction cuts (R9: not
// issue-bound), bank-partitioned replication (R10: sub-warp phases want the
// full crossbar), block/warp work-stealing (R11-12: overhead > skew tail),
// higher occupancy (R13), warp-perfect balance (R14), 4B quantization
// (calibrated error model: >= 1.7e-3 > 1e-3 budget).

#define NLOD 10

struct Params { const float* cb[NLOD]; };

// sizes = min(lod^2, 1024) for lods {7,8,11,14,18,23,30,38,50,64/65}
__host__ __device__ constexpr int H_SIZES(int l) {
    constexpr int s[NLOD] = {49, 64, 121, 196, 324, 529, 900, 1024, 1024, 1024};
    return s[l];
}
__host__ __device__ constexpr int H_OFFS(int l) {
    constexpr int o[NLOD] = {0, 49, 113, 234, 430, 754, 1283, 2183, 3207, 4231};
    return o[l];
}
constexpr int H_TOTAL = 5255;
constexpr int SMEM_BYTES = H_TOTAL * 8;   // 42,040 B (uint2 per entry)
constexpr int THREADS = 512;

template <int LAST_RES>
__global__ __launch_bounds__(THREADS, 2)
void hashgrid_kernel(const float* __restrict__ pts, Params prm,
                     float* __restrict__ out, int n)
{
    extern __shared__ uint2 scb[];   // entry: {half2(f0,f1), half2(f2,_)}

    // ---- Stage codebooks as packed fp16 (8 B/entry) ----
    #pragma unroll
    for (int l = 0; l < NLOD; l++) {
        const float* __restrict__ src = prm.cb[l];
        const int sz = H_SIZES(l);
        const int off = H_OFFS(l);
        for (int i = threadIdx.x; i < sz; i += THREADS) {
            __half2 h01 = __floats2half2_rn(src[3 * i], src[3 * i + 1]);
            __half2 h23 = __floats2half2_rn(src[3 * i + 2], 0.0f);
            uint2 v;
            v.x = *reinterpret_cast<unsigned*>(&h01);
            v.y = *reinterpret_cast<unsigned*>(&h23);
            scb[off + i] = v;
        }
    }
    __syncthreads();

    const int stride = gridDim.x * THREADS;
    for (int i = blockIdx.x * THREADS + threadIdx.x; i < n; i += stride) {
        const float px = pts[3 * i + 0];
        const float py = pts[3 * i + 1];
        const float pz = pts[3 * i + 2];
        float a0 = 0.0f, a1 = 0.0f, a2 = 0.0f;

        #pragma unroll
        for (int l = 0; l < NLOD; l++) {
            constexpr int RESA[NLOD] = {7, 8, 11, 14, 18, 23, 30, 38, 50, LAST_RES};
            const int R = RESA[l];
            const unsigned S = (unsigned)H_SIZES(l);   // compile-time -> magic mod
            const int O = H_OFFS(l);
            const float scale = (float)(R - 1);

            const float xs = px * scale, ys = py * scale, zs = pz * scale;
            int x0 = (int)xs; x0 = x0 > R - 2 ? R - 2 : x0;  // xs >= 0: trunc == floor
            int y0 = (int)ys; y0 = y0 > R - 2 ? R - 2 : y0;
            int z0 = (int)zs; z0 = z0 > R - 2 ? R - 2 : z0;
            const float wx = xs - (float)x0, wy = ys - (float)y0, wz = zs - (float)z0;
            const float ux = 1.0f - wx, uy = 1.0f - wy, uz = 1.0f - wz;

            // Instant-NGP primes: {1, 2654435761, 805459861}
            const unsigned hx0 = (unsigned)x0;
            const unsigned hx1 = hx0 + 1u;
            const unsigned hy0 = (unsigned)y0 * 2654435761u;
            const unsigned hy1 = hy0 + 2654435761u;
            const unsigned hz0 = (unsigned)z0 * 805459861u;
            const unsigned hz1 = hz0 + 805459861u;

            const float w00 = uy * uz, w01 = uy * wz, w10 = wy * uz, w11 = wy * wz;

            #define HG_CORNER(HX, HY, HZ, WX, WYZ)                           \
            {                                                                \
                const unsigned idx = ((HX) ^ (HY) ^ (HZ)) % S;               \
                const uint2 v = scb[O + (int)idx];                           \
                const __half2 h01 = *reinterpret_cast<const __half2*>(&v.x); \
                const __half  h2  = *reinterpret_cast<const __half*>(&v.y);  \
                const float2 f01 = __half22float2(h01);                      \
                const float  f2  = __half2float(h2);                         \
                const float w = (WX) * (WYZ);                                \
                a0 = fmaf(w, f01.x, a0);                                     \
                a1 = fmaf(w, f01.y, a1);                                     \
                a2 = fmaf(w, f2,    a2);                                     \
            }
            // corner order (i=x, j=y, k=z) matches OFFSETS enumeration
            HG_CORNER(hx0, hy0, hz0, ux, w00)
            HG_CORNER(hx0, hy0, hz1, ux, w01)
            HG_CORNER(hx0, hy1, hz0, ux, w10)
            HG_CORNER(hx0, hy1, hz1, ux, w11)
            HG_CORNER(hx1, hy0, hz0, wx, w00)
            HG_CORNER(hx1, hy0, hz1, wx, w01)
            HG_CORNER(hx1, hy1, hz0, wx, w10)
            HG_CORNER(hx1, hy1, hz1, wx, w11)
            #undef HG_CORNER
        }

        out[3 * i + 0] = a0;
        out[3 * i + 1] = a1;
        out[3 * i + 2] = a2;
    }
}

extern "C" void kernel_launch(void* const* d_in, const int* in_sizes, int n_in,
                              void* d_out, int out_size)
{
    const float* pts = (const float*)d_in[0];
    const int n = in_sizes[0] / 3;

    Params prm;
    for (int l = 0; l < NLOD; l++) prm.cb[l] = (const float*)d_in[1 + l];

    // Replicate the reference's LOD formula exactly in double precision:
    // 6*b^9 sits within fp noise of exactly 64.0; compute the floor the same
    // way numpy does and dispatch on the result.
    const double b = exp((log(64.0) - log(6.0)) / 9.0);
    const double v9 = 6.0 * pow(b, 9.0);
    const int last_res = (int)(1.0 + floor(v9));

    int sm_count = 0;
    cudaDeviceGetAttribute(&sm_count, cudaDevAttrMultiProcessorCount, 0);
    if (sm_count <= 0) sm_count = 148;
    const int blocks = sm_count * 2;  // 2 CTAs x 512 threads per SM

    float* out = (float*)d_out;

    if (last_res == 65) {
        cudaFuncSetAttribute(hashgrid_kernel<65>,
                             cudaFuncAttributeMaxDynamicSharedMemorySize, SMEM_BYTES);
        hashgrid_kernel<65><<<blocks, THREADS, SMEM_BYTES>>>(pts, prm, out, n);
    } else {
        cudaFuncSetAttribute(hashgrid_kernel<64>,
                             cudaFuncAttributeMaxDynamicSharedMemorySize, SMEM_BYTES);
        hashgrid_kernel<64><<<blocks, THREADS, SMEM_BYTES>>>(pts, prm, out, n);
    }
}